// round 6
// baseline (speedup 1.0000x reference)
#include <cuda_runtime.h>
#include <cuda_bf16.h>
#include <stdint.h>

// LinBnA_int on GB300 (compiled via compute_103 -> no tcgen05; use legacy mma.sync IMMA path).
// out[b,o] = clip((sum_k x[b,k]*W[o,k] + t[o]) >> (-n[o]), amin[o], amax[o]) stored as f32.
// Inputs arrive canonicalized (int32 observed); probe classifies, repack -> int8 scratch.

static constexpr int B_DIM   = 8192;
static constexpr int IN_DIM  = 4096;
static constexpr int OUT_DIM = 4096;

static constexpr int BM  = 128;            // M rows per CTA
static constexpr int BN  = 256;            // N cols per CTA
static constexpr int BKB = 64;             // K bytes per stage
static constexpr int KT  = IN_DIM / BKB;   // 64 stages
static constexpr int RS  = 80;             // SMEM row stride (64 data + 16 pad) -> conflict-free ldmatrix

// SMEM layout (bytes)
static constexpr int OFF_A0  = 0;                  // 128*80 = 10240
static constexpr int OFF_A1  = 10240;
static constexpr int OFF_B0  = 20480;              // 256*80 = 20480
static constexpr int OFF_B1  = 40960;
static constexpr int OFF_PAR = 61440;              // 4 * 256 * 4 = 4096
static constexpr int SMEM_TOTAL = 65536;

// mode: 0 = raw int8, 1 = int32, 2 = float32, 3 = bfloat16
__device__ int g_mode;
__device__ __align__(128) int8_t g_x[(size_t)B_DIM * IN_DIM];
__device__ __align__(128) int8_t g_w[(size_t)OUT_DIM * IN_DIM];

__global__ void probe_kernel(const void* x)
{
    if (threadIdx.x != 0) return;
    const uint32_t* w32 = (const uint32_t*)x;
    bool is_i32 = true, is_f32 = true;
    for (int i = 0; i < 32; i++) {
        uint32_t u = w32[i];
        int32_t v = (int32_t)u;
        if (!(v >= -128 && v < 128)) is_i32 = false;
        float f = __uint_as_float(u);
        if (!(isfinite(f) && f == truncf(f) && fabsf(f) <= 128.0f)) is_f32 = false;
    }
    bool is_b16 = true;
    const __nv_bfloat16* h = (const __nv_bfloat16*)x;
    for (int i = 0; i < 64; i++) {
        float f = __bfloat162float(h[i]);
        if (!(isfinite(f) && f == truncf(f) && fabsf(f) <= 128.0f)) is_b16 = false;
    }
    int m = 0;
    if (is_f32)      m = 2;
    else if (is_i32) m = 1;
    else if (is_b16) m = 3;
    g_mode = m;
}

__global__ void repack_kernel(const void* xsrc, const void* wsrc)
{
    const int m = g_mode;
    if (m == 0) return;
    const size_t NX = (size_t)B_DIM * IN_DIM;
    const size_t NW = (size_t)OUT_DIM * IN_DIM;
    const size_t total = NX + NW;
    const size_t stride = (size_t)gridDim.x * blockDim.x;
    for (size_t i = (size_t)blockIdx.x * blockDim.x + threadIdx.x; i < total; i += stride) {
        size_t xi; const void* src; int8_t* dst;
        if (i < NX) { xi = i;      src = xsrc; dst = g_x; }
        else        { xi = i - NX; src = wsrc; dst = g_w; }
        int v;
        if (m == 1)      v = ((const int*)src)[xi];
        else if (m == 2) v = (int)((const float*)src)[xi];
        else             v = (int)__bfloat162float(((const __nv_bfloat16*)src)[xi]);
        dst[xi] = (int8_t)v;
    }
}

// ---- helpers --------------------------------------------------------------

__device__ __forceinline__ uint32_t smem_u32(const void* p) {
    uint32_t a;
    asm("{ .reg .u64 t; cvta.to.shared.u64 t, %1; cvt.u32.u64 %0, t; }" : "=r"(a) : "l"(p));
    return a;
}
__device__ __forceinline__ void cp16(uint32_t dst, const void* src) {
    asm volatile("cp.async.cg.shared.global [%0], [%1], 16;" :: "r"(dst), "l"(src) : "memory");
}
__device__ __forceinline__ void cp_commit() { asm volatile("cp.async.commit_group;" ::: "memory"); }
template <int N> __device__ __forceinline__ void cp_wait() {
    asm volatile("cp.async.wait_group %0;" :: "n"(N) : "memory");
}
__device__ __forceinline__ void ldm_x4(uint32_t* r, uint32_t addr) {
    asm volatile("ldmatrix.sync.aligned.m8n8.x4.shared.b16 {%0,%1,%2,%3}, [%4];"
                 : "=r"(r[0]), "=r"(r[1]), "=r"(r[2]), "=r"(r[3]) : "r"(addr));
}
__device__ __forceinline__ void mma_s8(int* d, const uint32_t* a, uint32_t b0, uint32_t b1) {
    asm volatile(
        "mma.sync.aligned.m16n8k32.row.col.s32.s8.s8.s32 "
        "{%0,%1,%2,%3}, {%4,%5,%6,%7}, {%8,%9}, {%0,%1,%2,%3};"
        : "+r"(d[0]), "+r"(d[1]), "+r"(d[2]), "+r"(d[3])
        : "r"(a[0]), "r"(a[1]), "r"(a[2]), "r"(a[3]), "r"(b0), "r"(b1));
}

// ---- main GEMM kernel: 512 threads, 16 warps as 4(M) x 4(N), warp tile 32x64 ----

__global__ __launch_bounds__(512)
void linbna_imma_kernel(const int8_t* __restrict__ Xin,
                        const int8_t* __restrict__ Win,
                        const int*    __restrict__ tvec,
                        const int*    __restrict__ nvec,
                        const int*    __restrict__ amin,
                        const int*    __restrict__ amax,
                        float*        __restrict__ out)
{
    extern __shared__ char smem[];
    const uint32_t sb = smem_u32(smem);
    const int tid = threadIdx.x;
    const int wid = tid >> 5;
    const int lid = tid & 31;

    const int mode = g_mode;
    const int8_t* __restrict__ X = (mode == 0) ? Xin : g_x;
    const int8_t* __restrict__ W = (mode == 0) ? Win : g_w;

    const int brow = blockIdx.y * BM;
    const int bcol = blockIdx.x * BN;

    // Stage epilogue params
    if (tid < 256) {
        *(int*)(smem + OFF_PAR + 0    + tid * 4) = tvec[bcol + tid];
        *(int*)(smem + OFF_PAR + 1024 + tid * 4) = nvec[bcol + tid];
        *(int*)(smem + OFF_PAR + 2048 + tid * 4) = amin[bcol + tid];
        *(int*)(smem + OFF_PAR + 3072 + tid * 4) = amax[bcol + tid];
    }

    const uint32_t aoff[2] = { sb + OFF_A0, sb + OFF_A1 };
    const uint32_t boff[2] = { sb + OFF_B0, sb + OFF_B1 };

    // Loader: A 512 chunks (128 rows x 4x16B), B 1024 chunks (256 rows x 4x16B); 3 cp16/thread.
    auto load_stage = [&](int kt, int bb) {
        const int kbase = kt * BKB;
        {
            const int row = tid >> 2, ch = tid & 3;                 // A
            cp16(aoff[bb] + row * RS + ch * 16,
                 X + (size_t)(brow + row) * IN_DIM + kbase + ch * 16);
        }
#pragma unroll
        for (int i = 0; i < 2; i++) {                               // B
            const int c = tid + 512 * i;
            const int row = c >> 2, ch = c & 3;
            cp16(boff[bb] + row * RS + ch * 16,
                 W + (size_t)(bcol + row) * IN_DIM + kbase + ch * 16);
        }
        cp_commit();
    };

    const int wm = wid & 3;       // M group: rows wm*32 .. +31
    const int wn = wid >> 2;      // N group: cols wn*64 .. +63
    const int sub = lid >> 3;     // ldmatrix sub-matrix id (0..3)
    const int srow = lid & 7;     // row within sub-matrix

    int acc[2][8][4];
#pragma unroll
    for (int mt = 0; mt < 2; mt++)
#pragma unroll
        for (int nt = 0; nt < 8; nt++)
#pragma unroll
            for (int k = 0; k < 4; k++) acc[mt][nt][k] = 0;

    load_stage(0, 0);

    for (int kt = 0; kt < KT; kt++) {
        const int bb = kt & 1;
        if (kt + 1 < KT) { load_stage(kt + 1, bb ^ 1); cp_wait<1>(); }
        else             { cp_wait<0>(); }
        __syncthreads();

#pragma unroll
        for (int s = 0; s < 2; s++) {       // two k32 steps per 64B stage
            // A fragments: mt in {0,1}; sub-matrices (rows0-7,k-lo)(rows8-15,k-lo)(rows0-7,k-hi)(rows8-15,k-hi)
            uint32_t afr[2][4];
#pragma unroll
            for (int mt = 0; mt < 2; mt++) {
                const int row = wm * 32 + mt * 16 + (sub & 1) * 8 + srow;
                const int ch  = 2 * s + (sub >> 1);
                ldm_x4(afr[mt], aoff[bb] + row * RS + ch * 16);
            }
            // B fragments: 4 ldmatrix.x4, each covers 2 n-octets
            uint32_t bfr[4][4];
#pragma unroll
            for (int bq = 0; bq < 4; bq++) {
                const int nrow = wn * 64 + bq * 16 + (sub >> 1) * 8 + srow;
                const int ch   = 2 * s + (sub & 1);
                ldm_x4(bfr[bq], boff[bb] + nrow * RS + ch * 16);
            }
#pragma unroll
            for (int mt = 0; mt < 2; mt++)
#pragma unroll
                for (int nt = 0; nt < 8; nt++)
                    mma_s8(acc[mt][nt], afr[mt],
                           bfr[nt >> 1][(nt & 1) * 2], bfr[nt >> 1][(nt & 1) * 2 + 1]);
        }
        __syncthreads();
    }

    // Epilogue: acc[mt][nt] covers rows {wm*32+mt*16+(lid>>2), +8}, cols wn*64+nt*8+2*(lid&3)+{0,1}
    const int* sT  = (const int*)(smem + OFF_PAR);
    const int* sN  = (const int*)(smem + OFF_PAR + 1024);
    const int* sLo = (const int*)(smem + OFF_PAR + 2048);
    const int* sHi = (const int*)(smem + OFF_PAR + 3072);

    const int r0 = brow + wm * 32 + (lid >> 2);
    const int cb = wn * 64 + 2 * (lid & 3);

#pragma unroll
    for (int mt = 0; mt < 2; mt++) {
#pragma unroll
        for (int nt = 0; nt < 8; nt++) {
            const int c  = cb + nt * 8;              // CTA-local col
            const int gc = bcol + c;
            const int t0 = sT[c],  t1 = sT[c + 1];
            const int s0 = -sN[c], s1 = -sN[c + 1];
            const int l0 = sLo[c], l1 = sLo[c + 1];
            const int h0 = sHi[c], h1 = sHi[c + 1];

            int v00 = (acc[mt][nt][0] + t0) >> s0;  v00 = min(max(v00, l0), h0);
            int v01 = (acc[mt][nt][1] + t1) >> s1;  v01 = min(max(v01, l1), h1);
            int v10 = (acc[mt][nt][2] + t0) >> s0;  v10 = min(max(v10, l0), h0);
            int v11 = (acc[mt][nt][3] + t1) >> s1;  v11 = min(max(v11, l1), h1);

            const int ra = r0 + mt * 16;
            float2 qa = { (float)v00, (float)v01 };
            float2 qb = { (float)v10, (float)v11 };
            *(float2*)(out + (size_t)ra * OUT_DIM + gc)       = qa;
            *(float2*)(out + (size_t)(ra + 8) * OUT_DIM + gc) = qb;
        }
    }
}

extern "C" void kernel_launch(void* const* d_in, const int* in_sizes, int n_in,
                              void* d_out, int out_size)
{
    const void* x   = d_in[0];
    const void* w   = d_in[1];
    const int* t    = (const int*)d_in[2];
    const int* n    = (const int*)d_in[3];
    const int* lo   = (const int*)d_in[4];
    const int* hi   = (const int*)d_in[5];

    static bool attr_set = false;
    if (!attr_set) {
        cudaFuncSetAttribute(linbna_imma_kernel,
                             cudaFuncAttributeMaxDynamicSharedMemorySize, SMEM_TOTAL);
        attr_set = true;
    }

    probe_kernel<<<1, 32>>>(x);
    repack_kernel<<<1184, 256>>>(x, w);
    dim3 grid(OUT_DIM / BN, B_DIM / BM);   // (16, 64)
    linbna_imma_kernel<<<grid, 512, SMEM_TOTAL>>>((const int8_t*)x, (const int8_t*)w,
                                                  t, n, lo, hi, (float*)d_out);
}

// round 8
// speedup vs baseline: 1.9474x; 1.9474x over previous
#include <cuda_runtime.h>
#include <cuda_bf16.h>
#include <cuda_fp16.h>
#include <stdint.h>

// LinBnA_int on GB300, compiled via compute_103 (no tcgen05; s8 mma.sync is dp4a-emulated).
// Experiment: legacy fp16 HMMA path. int8 values are exact in fp16; f32 accumulation is
// exact below 2^24 (argued < 1e-5 rel_err overall). Repack canonicalized inputs -> fp16.

static constexpr int B_DIM   = 8192;
static constexpr int IN_DIM  = 4096;
static constexpr int OUT_DIM = 4096;

static constexpr int BM  = 128;            // M rows per CTA
static constexpr int BN  = 256;            // N cols per CTA
static constexpr int BKH = 32;             // K halves per stage (64 B per row)
static constexpr int KT  = IN_DIM / BKH;   // 128 stages
static constexpr int RS  = 80;             // SMEM row stride bytes (64 data + 16 pad)

// SMEM layout (bytes)
static constexpr int OFF_A0  = 0;                  // 128*80 = 10240
static constexpr int OFF_A1  = 10240;
static constexpr int OFF_B0  = 20480;              // 256*80 = 20480
static constexpr int OFF_B1  = 40960;
static constexpr int OFF_PAR = 61440;              // 4 * 256 * 4
static constexpr int SMEM_TOTAL = 65536;

// mode: 0 = raw int8, 1 = int32, 2 = float32, 3 = bfloat16
__device__ int g_mode;
__device__ __align__(128) __half g_x[(size_t)B_DIM * IN_DIM];     // 64 MB
__device__ __align__(128) __half g_w[(size_t)OUT_DIM * IN_DIM];   // 32 MB

__global__ void probe_kernel(const void* x)
{
    if (threadIdx.x != 0) return;
    const uint32_t* w32 = (const uint32_t*)x;
    bool is_i32 = true, is_f32 = true;
    for (int i = 0; i < 32; i++) {
        uint32_t u = w32[i];
        int32_t v = (int32_t)u;
        if (!(v >= -128 && v < 128)) is_i32 = false;
        float f = __uint_as_float(u);
        if (!(isfinite(f) && f == truncf(f) && fabsf(f) <= 128.0f)) is_f32 = false;
    }
    bool is_b16 = true;
    const __nv_bfloat16* h = (const __nv_bfloat16*)x;
    for (int i = 0; i < 64; i++) {
        float f = __bfloat162float(h[i]);
        if (!(isfinite(f) && f == truncf(f) && fabsf(f) <= 128.0f)) is_b16 = false;
    }
    int m = 0;
    if (is_f32)      m = 2;
    else if (is_i32) m = 1;
    else if (is_b16) m = 3;
    g_mode = m;
}

// Converts x and W (any encoding, including raw int8) into fp16 scratch.
__global__ void repack_kernel(const void* xsrc, const void* wsrc)
{
    const int m = g_mode;
    const size_t NX = (size_t)B_DIM * IN_DIM;
    const size_t NW = (size_t)OUT_DIM * IN_DIM;
    const size_t total = NX + NW;
    const size_t stride = (size_t)gridDim.x * blockDim.x;
    for (size_t i = (size_t)blockIdx.x * blockDim.x + threadIdx.x; i < total; i += stride) {
        size_t xi; const void* src; __half* dst;
        if (i < NX) { xi = i;      src = xsrc; dst = g_x; }
        else        { xi = i - NX; src = wsrc; dst = g_w; }
        int v;
        if (m == 0)      v = (int)((const int8_t*)src)[xi];
        else if (m == 1) v = ((const int*)src)[xi];
        else if (m == 2) v = (int)((const float*)src)[xi];
        else             v = (int)__bfloat162float(((const __nv_bfloat16*)src)[xi]);
        dst[xi] = __int2half_rn(v);
    }
}

// ---- helpers --------------------------------------------------------------

__device__ __forceinline__ uint32_t smem_u32(const void* p) {
    uint32_t a;
    asm("{ .reg .u64 t; cvta.to.shared.u64 t, %1; cvt.u32.u64 %0, t; }" : "=r"(a) : "l"(p));
    return a;
}
__device__ __forceinline__ void cp16(uint32_t dst, const void* src) {
    asm volatile("cp.async.cg.shared.global [%0], [%1], 16;" :: "r"(dst), "l"(src) : "memory");
}
__device__ __forceinline__ void cp_commit() { asm volatile("cp.async.commit_group;" ::: "memory"); }
template <int N> __device__ __forceinline__ void cp_wait() {
    asm volatile("cp.async.wait_group %0;" :: "n"(N) : "memory");
}
__device__ __forceinline__ void ldm_x4(uint32_t* r, uint32_t addr) {
    asm volatile("ldmatrix.sync.aligned.m8n8.x4.shared.b16 {%0,%1,%2,%3}, [%4];"
                 : "=r"(r[0]), "=r"(r[1]), "=r"(r[2]), "=r"(r[3]) : "r"(addr));
}
__device__ __forceinline__ void mma_f16(float* d, const uint32_t* a, uint32_t b0, uint32_t b1) {
    asm volatile(
        "mma.sync.aligned.m16n8k16.row.col.f32.f16.f16.f32 "
        "{%0,%1,%2,%3}, {%4,%5,%6,%7}, {%8,%9}, {%0,%1,%2,%3};"
        : "+f"(d[0]), "+f"(d[1]), "+f"(d[2]), "+f"(d[3])
        : "r"(a[0]), "r"(a[1]), "r"(a[2]), "r"(a[3]), "r"(b0), "r"(b1));
}

// ---- main GEMM: 512 threads, 16 warps as 4(M) x 4(N), warp tile 32x64 -----

__global__ __launch_bounds__(512)
void linbna_hmma_kernel(const int* __restrict__ tvec,
                        const int* __restrict__ nvec,
                        const int* __restrict__ amin,
                        const int* __restrict__ amax,
                        float*     __restrict__ out)
{
    extern __shared__ char smem[];
    const uint32_t sb = smem_u32(smem);
    const int tid = threadIdx.x;
    const int wid = tid >> 5;
    const int lid = tid & 31;

    const __half* __restrict__ X = g_x;
    const __half* __restrict__ W = g_w;

    const int brow = blockIdx.y * BM;
    const int bcol = blockIdx.x * BN;

    if (tid < 256) {
        *(int*)(smem + OFF_PAR + 0    + tid * 4) = tvec[bcol + tid];
        *(int*)(smem + OFF_PAR + 1024 + tid * 4) = nvec[bcol + tid];
        *(int*)(smem + OFF_PAR + 2048 + tid * 4) = amin[bcol + tid];
        *(int*)(smem + OFF_PAR + 3072 + tid * 4) = amax[bcol + tid];
    }

    const uint32_t aoff[2] = { sb + OFF_A0, sb + OFF_A1 };
    const uint32_t boff[2] = { sb + OFF_B0, sb + OFF_B1 };

    // Per stage: A 128 rows x 4 chunks(16B) = 512 cp16; B 256 x 4 = 1024 cp16.
    auto load_stage = [&](int kt, int bb) {
        const int kbase = kt * BKH;   // element offset (halves)
        {
            const int row = tid >> 2, ch = tid & 3;
            cp16(aoff[bb] + row * RS + ch * 16,
                 X + (size_t)(brow + row) * IN_DIM + kbase + ch * 8);
        }
#pragma unroll
        for (int i = 0; i < 2; i++) {
            const int c = tid + 512 * i;
            const int row = c >> 2, ch = c & 3;
            cp16(boff[bb] + row * RS + ch * 16,
                 W + (size_t)(bcol + row) * IN_DIM + kbase + ch * 8);
        }
        cp_commit();
    };

    const int wm = wid & 3;       // M group (rows wm*32..+31)
    const int wn = wid >> 2;      // N group (cols wn*64..+63)
    const int sub = lid >> 3;     // ldmatrix sub-matrix id
    const int srow = lid & 7;

    float acc[2][8][4];
#pragma unroll
    for (int mt = 0; mt < 2; mt++)
#pragma unroll
        for (int nt = 0; nt < 8; nt++)
#pragma unroll
            for (int k = 0; k < 4; k++) acc[mt][nt][k] = 0.0f;

    load_stage(0, 0);

    for (int kt = 0; kt < KT; kt++) {
        const int bb = kt & 1;
        if (kt + 1 < KT) { load_stage(kt + 1, bb ^ 1); cp_wait<1>(); }
        else             { cp_wait<0>(); }
        __syncthreads();

#pragma unroll
        for (int s = 0; s < 2; s++) {       // two k16 steps per 64B stage
            uint32_t afr[2][4];
#pragma unroll
            for (int mt = 0; mt < 2; mt++) {
                const int row = wm * 32 + mt * 16 + (sub & 1) * 8 + srow;
                const int ch  = 2 * s + (sub >> 1);     // 16B chunk = 8 k-halves
                ldm_x4(afr[mt], aoff[bb] + row * RS + ch * 16);
            }
            uint32_t bfr[4][4];
#pragma unroll
            for (int bq = 0; bq < 4; bq++) {
                const int nrow = wn * 64 + bq * 16 + (sub >> 1) * 8 + srow;
                const int ch   = 2 * s + (sub & 1);
                ldm_x4(bfr[bq], boff[bb] + nrow * RS + ch * 16);
            }
#pragma unroll
            for (int mt = 0; mt < 2; mt++)
#pragma unroll
                for (int nt = 0; nt < 8; nt++)
                    mma_f16(acc[mt][nt], afr[mt],
                            bfr[nt >> 1][(nt & 1) * 2], bfr[nt >> 1][(nt & 1) * 2 + 1]);
        }
        __syncthreads();
    }

    // Epilogue: rows wm*32+mt*16+(lid>>2)+{0,8}, cols wn*64+nt*8+2*(lid&3)+{0,1}
    const int* sT  = (const int*)(smem + OFF_PAR);
    const int* sN  = (const int*)(smem + OFF_PAR + 1024);
    const int* sLo = (const int*)(smem + OFF_PAR + 2048);
    const int* sHi = (const int*)(smem + OFF_PAR + 3072);

    const int r0 = brow + wm * 32 + (lid >> 2);
    const int cb = wn * 64 + 2 * (lid & 3);

#pragma unroll
    for (int mt = 0; mt < 2; mt++) {
#pragma unroll
        for (int nt = 0; nt < 8; nt++) {
            const int c  = cb + nt * 8;
            const int gc = bcol + c;
            const int t0 = sT[c],  t1 = sT[c + 1];
            const int s0 = -sN[c], s1 = -sN[c + 1];
            const int l0 = sLo[c], l1 = sLo[c + 1];
            const int h0 = sHi[c], h1 = sHi[c + 1];

            int v00 = (__float2int_rn(acc[mt][nt][0]) + t0) >> s0;  v00 = min(max(v00, l0), h0);
            int v01 = (__float2int_rn(acc[mt][nt][1]) + t1) >> s1;  v01 = min(max(v01, l1), h1);
            int v10 = (__float2int_rn(acc[mt][nt][2]) + t0) >> s0;  v10 = min(max(v10, l0), h0);
            int v11 = (__float2int_rn(acc[mt][nt][3]) + t1) >> s1;  v11 = min(max(v11, l1), h1);

            const int ra = r0 + mt * 16;
            float2 qa = { (float)v00, (float)v01 };
            float2 qb = { (float)v10, (float)v11 };
            *(float2*)(out + (size_t)ra * OUT_DIM + gc)       = qa;
            *(float2*)(out + (size_t)(ra + 8) * OUT_DIM + gc) = qb;
        }
    }
}

extern "C" void kernel_launch(void* const* d_in, const int* in_sizes, int n_in,
                              void* d_out, int out_size)
{
    const void* x   = d_in[0];
    const void* w   = d_in[1];
    const int* t    = (const int*)d_in[2];
    const int* n    = (const int*)d_in[3];
    const int* lo   = (const int*)d_in[4];
    const int* hi   = (const int*)d_in[5];

    static bool attr_set = false;
    if (!attr_set) {
        cudaFuncSetAttribute(linbna_hmma_kernel,
                             cudaFuncAttributeMaxDynamicSharedMemorySize, SMEM_TOTAL);
        attr_set = true;
    }

    probe_kernel<<<1, 32>>>(x);
    repack_kernel<<<1184, 256>>>(x, w);
    dim3 grid(OUT_DIM / BN, B_DIM / BM);   // (16, 64)
    linbna_hmma_kernel<<<grid, 512, SMEM_TOTAL>>>(t, n, lo, hi, (float*)d_out);
}